// round 12
// baseline (speedup 1.0000x reference)
#include <cuda_runtime.h>
#include <cuda_fp16.h>
#include <cstdint>
#include <math.h>

// Problem constants
#define NB 8
#define NL 8
#define NK 32
#define NP 64
#define NC 256

#define NWE 256              // ego windows
#define NWO 2048             // other windows
#define EGO_OUT_SZ (NWE*NC*NP)

// A tile: 64 rows x 256 halves, pitch 264 halves (528B) -> ldmatrix bank group
// (m + u) mod 8, conflict-free for every 8-row phase.
#define A_PITCH 264
#define A_BYTES (64 * 528)          // 33792
#define B_BYTES 8192                // 32k x 128n halves, 256B rows
#define POOL_BYTES (A_BYTES + 2 * B_BYTES)   // 50176

// Intermediates (static device memory; no allocation)
__device__ float g_qv_e[(size_t)NWE * NP * 512];
__device__ float g_kv_o[(size_t)NWE * NP * NL * 512];
__device__ float g_o_e [(size_t)NWE * NP * NC];
__device__ __half g_Whe[256 * 768];    // fp16 QKV weights
__device__ __half g_Who[256 * 768];
__device__ __half g_Whoe[256 * 256];   // fp16 out-proj weights
__device__ __half g_Whoo[256 * 256];

__device__ __forceinline__ uint32_t smem_u32(const void* p) {
    uint32_t a;
    asm("{ .reg .u64 t; cvta.to.shared.u64 t, %1; cvt.u32.u64 %0, t; }" : "=r"(a) : "l"(p));
    return a;
}
__device__ __forceinline__ uint32_t pkh2(float x, float y) {
    __half2 h = __floats2half2_rn(x, y);
    return *(uint32_t*)&h;
}

#define LDMX4(r, addr) \
    asm volatile("ldmatrix.sync.aligned.m8n8.x4.shared.b16 {%0,%1,%2,%3}, [%4];" \
        : "=r"((r)[0]), "=r"((r)[1]), "=r"((r)[2]), "=r"((r)[3]) : "r"(addr))
#define LDMX4T(r, addr) \
    asm volatile("ldmatrix.sync.aligned.m8n8.x4.trans.shared.b16 {%0,%1,%2,%3}, [%4];" \
        : "=r"((r)[0]), "=r"((r)[1]), "=r"((r)[2]), "=r"((r)[3]) : "r"(addr))
#define MMA16816(d, a, b0, b1) \
    asm volatile("mma.sync.aligned.m16n8k16.row.col.f32.f16.f16.f32 " \
        "{%0,%1,%2,%3}, {%4,%5,%6,%7}, {%8,%9}, {%0,%1,%2,%3};" \
        : "+f"((d)[0]), "+f"((d)[1]), "+f"((d)[2]), "+f"((d)[3]) \
        : "r"((a)[0]), "r"((a)[1]), "r"((a)[2]), "r"((a)[3]), "r"(b0), "r"(b1))

// shared mainloop body: ldmatrix A (persistent) + ldmatrix.trans B (buffer) + MMA
#define GEMM_CHUNK(acc, as_b, bs_cur, mbase, nbase, lane, c)                         \
    do {                                                                             \
        _Pragma("unroll")                                                            \
        for (int ks = 0; ks < 2; ks++) {                                             \
            uint32_t a[2][4];                                                        \
            _Pragma("unroll")                                                        \
            for (int mt = 0; mt < 2; mt++) {                                         \
                uint32_t ad = (as_b) + ((mbase) + mt * 16 + ((lane) & 15)) * 528     \
                            + ((c) * 4 + ks * 2 + ((lane) >> 4)) * 16;               \
                LDMX4(a[mt], ad);                                                    \
            }                                                                        \
            uint32_t b[4][4];                                                        \
            _Pragma("unroll")                                                        \
            for (int ng = 0; ng < 4; ng++) {                                         \
                const int kk = ks * 16 + ((lane) & 7) + (((lane) >> 4) << 3);        \
                const int useg = (((nbase) + ng * 16) >> 3) + (((lane) >> 3) & 1);   \
                uint32_t bd = (bs_cur) + kk * 256 + (useg ^ (kk & 7)) * 16;          \
                LDMX4T(b[ng], bd);                                                   \
            }                                                                        \
            _Pragma("unroll")                                                        \
            for (int ng = 0; ng < 4; ng++)                                           \
                _Pragma("unroll")                                                    \
                for (int h2 = 0; h2 < 2; h2++) {                                     \
                    const int nt = ng * 2 + h2;                                      \
                    _Pragma("unroll")                                                \
                    for (int mt = 0; mt < 2; mt++)                                   \
                        MMA16816(acc[mt][nt], a[mt], b[ng][h2], b[ng][2 + h2]);      \
                }                                                                    \
        }                                                                            \
    } while (0)

// ---------------------------------------------------------------------------
// Kernel 0: convert all weights to fp16 (once per launch, tiny)
// ---------------------------------------------------------------------------
__global__ void cvt_w(const float* __restrict__ We, const float* __restrict__ Wo,
                      const float* __restrict__ Woe, const float* __restrict__ Woo)
{
    int i = blockIdx.x * 256 + threadIdx.x;
    if (i < 256 * 768) {
        g_Whe[i] = __float2half_rn(We[i]);
        g_Who[i] = __float2half_rn(Wo[i]);
    }
    if (i < 256 * 256) {
        g_Whoe[i] = __float2half_rn(Woe[i]);
        g_Whoo[i] = __float2half_rn(Woo[i]);
    }
}

// ---------------------------------------------------------------------------
// Kernel 1: QKV projections. A staged once (fp16, conflict-free pitch), B
// double-buffered with register prefetch, one sync per chunk.
// Grid: x = window (ego then other), y = 128-col group. 128 thr / 4 warps.
// ---------------------------------------------------------------------------
__global__ __launch_bounds__(128) void qkv_f16(
    const float* __restrict__ ego, const float* __restrict__ other)
{
    extern __shared__ __align__(16) char pool[];
    __half* As = (__half*)pool;
    char* Bbuf[2] = { pool + A_BYTES, pool + A_BYTES + B_BYTES };

    const int w = blockIdx.x;
    const int nb = blockIdx.y;
    const bool is_ego = (w < NWE);
    const float* src = is_ego ? ego + (size_t)w * (NC * NP)
                              : other + (size_t)(w - NWE) * (NC * NP);
    const __half* Wh = is_ego ? g_Whe : g_Who;
    const int colbase = is_ego ? (nb < 2 ? nb * 128 : nb * 128 + 256) : (256 + nb * 128);

    const int t = threadIdx.x;
    const int warp = t >> 5, lane = t & 31;
    const int mbase = (warp >> 1) * 32;
    const int nbase = (warp & 1) * 64;
    const uint32_t as_b = smem_u32(As);
    const uint32_t bs_b0 = smem_u32(Bbuf[0]), bs_b1 = smem_u32(Bbuf[1]);

    // stage A once: 64 px x 256 k, unit = 8 consecutive k for one pixel
    #pragma unroll
    for (int ii = 0; ii < 16; ii++) {
        const int i = t + ii * 128;
        const int u = i >> 6, m = i & 63;      // u: k-unit 0..31, m: pixel
        const float* r = src + (size_t)(u * 8) * NP + m;
        float v0 = r[0 * NP], v1 = r[1 * NP], v2 = r[2 * NP], v3 = r[3 * NP];
        float v4 = r[4 * NP], v5 = r[5 * NP], v6 = r[6 * NP], v7 = r[7 * NP];
        *(uint4*)&As[m * A_PITCH + u * 8] =
            make_uint4(pkh2(v0, v1), pkh2(v2, v3), pkh2(v4, v5), pkh2(v6, v7));
    }

    uint4 pb[4];
    // prologue: B chunk 0
    #pragma unroll
    for (int ii = 0; ii < 4; ii++) {
        const int i = t + ii * 128, k = i >> 4, u = i & 15;
        pb[ii] = *(const uint4*)&Wh[(size_t)k * 768 + colbase + u * 8];
    }
    #pragma unroll
    for (int ii = 0; ii < 4; ii++) {
        const int i = t + ii * 128, k = i >> 4, u = i & 15;
        *(uint4*)(Bbuf[0] + k * 256 + (u ^ (k & 7)) * 16) = pb[ii];
    }
    __syncthreads();

    float acc[2][8][4];
    #pragma unroll
    for (int mt = 0; mt < 2; mt++)
        #pragma unroll
        for (int nt = 0; nt < 8; nt++)
            #pragma unroll
            for (int r = 0; r < 4; r++) acc[mt][nt][r] = 0.f;

    #pragma unroll
    for (int c = 0; c < 8; c++) {
        if (c < 7) {                       // prefetch next B chunk (LDG only)
            #pragma unroll
            for (int ii = 0; ii < 4; ii++) {
                const int i = t + ii * 128, k = i >> 4, u = i & 15;
                pb[ii] = *(const uint4*)&Wh[(size_t)((c + 1) * 32 + k) * 768 + colbase + u * 8];
            }
        }
        const uint32_t bs_cur = (c & 1) ? bs_b1 : bs_b0;
        GEMM_CHUNK(acc, as_b, bs_cur, mbase, nbase, lane, c);
        if (c < 7) {
            char* nbuf = Bbuf[(c + 1) & 1];
            #pragma unroll
            for (int ii = 0; ii < 4; ii++) {
                const int i = t + ii * 128, k = i >> 4, u = i & 15;
                *(uint4*)(nbuf + k * 256 + (u ^ (k & 7)) * 16) = pb[ii];
            }
        }
        __syncthreads();
    }

    // epilogue: scatter C frags
    const int qid = lane >> 2, tid4 = lane & 3;
    int wo = w - NWE;
    int bo = wo >> 8, l = (wo >> 5) & 7, kk2 = wo & 31;
    const int bk = is_ego ? w : (bo * NK + kk2);

    #pragma unroll
    for (int mt = 0; mt < 2; mt++) {
        int px = mbase + mt * 16 + qid;
        #pragma unroll
        for (int nt = 0; nt < 8; nt++) {
            int col = nb * 128 + nbase + nt * 8 + 2 * tid4;
            float2 v0 = make_float2(acc[mt][nt][0], acc[mt][nt][1]);
            float2 v1 = make_float2(acc[mt][nt][2], acc[mt][nt][3]);
            if (is_ego) {
                size_t i0 = ((size_t)bk * NP + px) * 512 + col;
                size_t i1 = ((size_t)bk * NP + px + 8) * 512 + col;
                *(float2*)&g_qv_e[i0] = v0;
                *(float2*)&g_qv_e[i1] = v1;
            } else {
                size_t i0 = (((size_t)bk * NP + px) * NL + l) * 512 + col;
                size_t i1 = (((size_t)bk * NP + px + 8) * NL + l) * 512 + col;
                *(float2*)&g_kv_o[i0] = v0;
                *(float2*)&g_kv_o[i1] = v1;
            }
        }
    }
}

// ---------------------------------------------------------------------------
// Kernel 2: attention (unchanged). q_o/k_e path is the identity (softmax over
// singleton ego axis == 1), so only the ego-query path is computed.
// ---------------------------------------------------------------------------
__global__ __launch_bounds__(256) void attn_kernel()
{
    const int pix = blockIdx.x;
    const int t = threadIdx.x;

    const float q = g_qv_e[(size_t)pix * 512 + t];
    const size_t base = (size_t)pix * NL * 512;
    const float scale = 0.17677669529663687f;

    float scores[NL];
    #pragma unroll
    for (int l = 0; l < NL; l++) {
        float prod = q * g_kv_o[base + l * 512 + t];
        #pragma unroll
        for (int off = 16; off > 0; off >>= 1)
            prod += __shfl_xor_sync(0xffffffffu, prod, off);
        scores[l] = prod * scale;
    }
    float mx = scores[0];
    #pragma unroll
    for (int l = 1; l < NL; l++) mx = fmaxf(mx, scores[l]);
    float sum = 0.f;
    #pragma unroll
    for (int l = 0; l < NL; l++) { scores[l] = __expf(scores[l] - mx); sum += scores[l]; }
    const float inv = 1.f / sum;
    float o = 0.f;
    #pragma unroll
    for (int l = 0; l < NL; l++)
        o += scores[l] * inv * g_kv_o[base + l * 512 + 256 + t];
    g_o_e[(size_t)pix * NC + t] = o;
}

// ---------------------------------------------------------------------------
// Kernel 3: output projections. Same stage-A-once + pipelined-B design.
// Grid: x = bk*2+mode, y = n-half. mode 1: o_o == v_e (softmax over singleton
// axis == identity), identical for all l -> compute once, fan out 8 stores.
// ---------------------------------------------------------------------------
__global__ __launch_bounds__(128) void out_f16(
    const float* __restrict__ boe, const float* __restrict__ boo,
    float* __restrict__ out)
{
    extern __shared__ __align__(16) char pool[];
    __half* As = (__half*)pool;
    char* Bbuf[2] = { pool + A_BYTES, pool + A_BYTES + B_BYTES };

    const int x = blockIdx.x;
    const int nb = blockIdx.y;
    const int bk = x >> 1;
    const int mode = x & 1;
    const __half* Wh  = mode ? g_Whoo : g_Whoe;
    const float* bias = mode ? boo : boe;
    const float* asrc = mode ? (g_qv_e + (size_t)bk * NP * 512 + 256)
                             : (g_o_e  + (size_t)bk * NP * NC);
    const size_t astride = mode ? 512 : 256;
    const int colbase = nb * 128;

    const int t = threadIdx.x;
    const int warp = t >> 5, lane = t & 31;
    const int mbase = (warp >> 1) * 32;
    const int nbase = (warp & 1) * 64;
    const uint32_t as_b = smem_u32(As);
    const uint32_t bs_b0 = smem_u32(Bbuf[0]), bs_b1 = smem_u32(Bbuf[1]);

    // stage A once: 64 rows x 256 k, k-contiguous source -> vector loads
    #pragma unroll
    for (int ii = 0; ii < 16; ii++) {
        const int i = t + ii * 128;
        const int u = i & 31, m = i >> 5;
        const float* r = asrc + (size_t)m * astride + u * 8;
        float4 u0 = *(const float4*)r;
        float4 u1 = *(const float4*)(r + 4);
        *(uint4*)&As[m * A_PITCH + u * 8] =
            make_uint4(pkh2(u0.x, u0.y), pkh2(u0.z, u0.w),
                       pkh2(u1.x, u1.y), pkh2(u1.z, u1.w));
    }

    uint4 pb[4];
    #pragma unroll
    for (int ii = 0; ii < 4; ii++) {
        const int i = t + ii * 128, k = i >> 4, u = i & 15;
        pb[ii] = *(const uint4*)&Wh[(size_t)k * 256 + colbase + u * 8];
    }
    #pragma unroll
    for (int ii = 0; ii < 4; ii++) {
        const int i = t + ii * 128, k = i >> 4, u = i & 15;
        *(uint4*)(Bbuf[0] + k * 256 + (u ^ (k & 7)) * 16) = pb[ii];
    }
    __syncthreads();

    float acc[2][8][4];
    #pragma unroll
    for (int mt = 0; mt < 2; mt++)
        #pragma unroll
        for (int nt = 0; nt < 8; nt++)
            #pragma unroll
            for (int r = 0; r < 4; r++) acc[mt][nt][r] = 0.f;

    #pragma unroll
    for (int c = 0; c < 8; c++) {
        if (c < 7) {
            #pragma unroll
            for (int ii = 0; ii < 4; ii++) {
                const int i = t + ii * 128, k = i >> 4, u = i & 15;
                pb[ii] = *(const uint4*)&Wh[(size_t)((c + 1) * 32 + k) * 256 + colbase + u * 8];
            }
        }
        const uint32_t bs_cur = (c & 1) ? bs_b1 : bs_b0;
        GEMM_CHUNK(acc, as_b, bs_cur, mbase, nbase, lane, c);
        if (c < 7) {
            char* nbuf = Bbuf[(c + 1) & 1];
            #pragma unroll
            for (int ii = 0; ii < 4; ii++) {
                const int i = t + ii * 128, k = i >> 4, u = i & 15;
                *(uint4*)(nbuf + k * 256 + (u ^ (k & 7)) * 16) = pb[ii];
            }
        }
        __syncthreads();
    }

    // transpose through smem (Cs overlays the A/B pool; last sync above
    // separates the final MMA's smem reads from these writes)
    float* Cs = (float*)pool;   // 128 * 68 * 4 = 34816 <= POOL_BYTES
    const int qid = lane >> 2, tid4 = lane & 3;
    #pragma unroll
    for (int mt = 0; mt < 2; mt++) {
        const int p = mbase + mt * 16 + qid;
        #pragma unroll
        for (int nt = 0; nt < 8; nt++) {
            const int n = nbase + nt * 8 + 2 * tid4;
            Cs[(n    ) * 68 + p    ] = acc[mt][nt][0];
            Cs[(n + 1) * 68 + p    ] = acc[mt][nt][1];
            Cs[(n    ) * 68 + p + 8] = acc[mt][nt][2];
            Cs[(n + 1) * 68 + p + 8] = acc[mt][nt][3];
        }
    }
    __syncthreads();

    // coalesced write: thread t owns cout = colbase + t, 64 p-floats (+bias)
    {
        const int cout = colbase + t;
        const float bv = bias[cout];
        if (mode == 0) {
            float* dst = out + ((size_t)bk * NC + cout) * NP;
            #pragma unroll
            for (int i = 0; i < 16; i++) {
                float4 v = *(float4*)&Cs[t * 68 + 4 * i];
                *(float4*)&dst[4 * i] =
                    make_float4(v.x + bv, v.y + bv, v.z + bv, v.w + bv);
            }
        } else {
            const int b = bk >> 5, k = bk & 31;
            #pragma unroll
            for (int i = 0; i < 16; i++) {
                float4 v = *(float4*)&Cs[t * 68 + 4 * i];
                float4 vb = make_float4(v.x + bv, v.y + bv, v.z + bv, v.w + bv);
                #pragma unroll
                for (int l = 0; l < NL; l++) {
                    size_t idx = (size_t)EGO_OUT_SZ
                               + ((size_t)((b * NL + l) * NK + k) * NC + cout) * NP + 4 * i;
                    *(float4*)&out[idx] = vb;
                }
            }
        }
    }
}

extern "C" void kernel_launch(void* const* d_in, const int* in_sizes, int n_in,
                              void* d_out, int out_size)
{
    const float* ego   = (const float*)d_in[0];
    const float* other = (const float*)d_in[1];
    const float* Wqe   = (const float*)d_in[2];
    const float* Wqo   = (const float*)d_in[3];
    const float* Woe   = (const float*)d_in[4];
    const float* boe   = (const float*)d_in[5];
    const float* Woo   = (const float*)d_in[6];
    const float* boo   = (const float*)d_in[7];
    float* out = (float*)d_out;

    cudaFuncSetAttribute(qkv_f16, cudaFuncAttributeMaxDynamicSharedMemorySize, POOL_BYTES);
    cudaFuncSetAttribute(out_f16, cudaFuncAttributeMaxDynamicSharedMemorySize, POOL_BYTES);

    cvt_w<<<768, 256>>>(Wqe, Wqo, Woe, Woo);
    dim3 qgrid(NWE + NWO, 4);
    qkv_f16<<<qgrid, 128, POOL_BYTES>>>(ego, other);
    attn_kernel<<<NWE * NP, 256>>>();
    dim3 ogrid(NWE * 2, 2);
    out_f16<<<ogrid, 128, POOL_BYTES>>>(boe, boo, out);
}